// round 11
// baseline (speedup 1.0000x reference)
#include <cuda_runtime.h>
#include <math.h>

// ---------------- problem constants ----------------
#define BB   32
#define TT   4096
#define AD   128
#define SS   100
#define BDM  10
#define HH   50
#define DD   30
#define NQ   25            // S/4 float4 "quads"
#define GSTEP 32           // timesteps per group
#define NGR  (TT / GSTEP)  // 128 groups
#define RINGG 8            // ring slots (groups)
#define PF   4             // producer prefetch distance
#define SROW 33            // float4 per q-row in one ring slot (32 + pad)
#define BTSW 104           // bts stride (words per group, 100 used)
#define FULLM 0xffffffffu

// ---------------- global scratch ----------------
__device__ __align__(16) float4 g_simsT[(size_t)BB * NQ * TT];  // [b][q][t]
__device__ __align__(16) float  g_z[(size_t)BB * TT * BDM];

// =====================================================================
// Kernel 1: z = mlp(x); sims stored quad-transposed [b][q][t]
// =====================================================================
__global__ void k_project(const float* __restrict__ x, const float* __restrict__ c,
                          const float* __restrict__ w1, const float* __restrict__ b1,
                          const float* __restrict__ w2, const float* __restrict__ b2,
                          const float* __restrict__ w3, const float* __restrict__ b3)
{
    __shared__ float w1s[BDM * AD];
    __shared__ float cs[BDM * SS];
    __shared__ float w2s[BDM * BDM], w3s[BDM * BDM];
    __shared__ float b1s[BDM], b2s[BDM], b3s[BDM];

    int tid = threadIdx.x;
    for (int i = tid; i < BDM * AD; i += 256) w1s[i] = w1[i];
    for (int i = tid; i < BDM * SS; i += 256) cs[i] = c[i];
    if (tid < BDM * BDM) { w2s[tid] = w2[tid]; w3s[tid] = w3[tid]; }
    if (tid < BDM) { b1s[tid] = b1[tid]; b2s[tid] = b2[tid]; b3s[tid] = b3[tid]; }
    __syncthreads();

    int gtid = blockIdx.x * 256 + tid;         // b*T + t
    int b = gtid >> 12;
    int t = gtid & (TT - 1);
    const float4* xr = (const float4*)(x + (size_t)gtid * AD);

    float z1[BDM];
#pragma unroll
    for (int d = 0; d < BDM; d++) z1[d] = b1s[d];

#pragma unroll 8
    for (int kk = 0; kk < AD / 4; ++kk) {
        float4 xv = xr[kk];
#pragma unroll
        for (int d = 0; d < BDM; d++) {
            float4 wv = ((const float4*)w1s)[d * (AD / 4) + kk];
            z1[d] += xv.x * wv.x + xv.y * wv.y + xv.z * wv.z + xv.w * wv.w;
        }
    }
#pragma unroll
    for (int d = 0; d < BDM; d++) z1[d] = fmaxf(z1[d], 0.0f);

    float z2[BDM];
#pragma unroll
    for (int d = 0; d < BDM; d++) {
        float a = b2s[d];
#pragma unroll
        for (int e = 0; e < BDM; e++) a += z1[e] * w2s[d * BDM + e];
        z2[d] = fmaxf(a, 0.0f);
    }
    float z3[BDM];
#pragma unroll
    for (int d = 0; d < BDM; d++) {
        float a = b3s[d];
#pragma unroll
        for (int e = 0; e < BDM; e++) a += z2[e] * w3s[d * BDM + e];
        z3[d] = a;
    }

    float* zo = g_z + (size_t)gtid * BDM;
#pragma unroll
    for (int d = 0; d < BDM; d++) zo[d] = z3[d];

#pragma unroll
    for (int q = 0; q < NQ; ++q) {
        float4 a = make_float4(0.f, 0.f, 0.f, 0.f);
#pragma unroll
        for (int d = 0; d < BDM; d++) {
            float zv = z3[d];
            float4 cv = ((const float4*)cs)[d * NQ + q];
            a.x += zv * cv.x; a.y += zv * cv.y;
            a.z += zv * cv.z; a.w += zv * cv.w;
        }
        g_simsT[((size_t)b * NQ + q) * TT + t] = a;   // coalesced over t
    }
}

// =====================================================================
// Kernel 2: 4 consumer warps (25 states each, 1 state/lane) in a
// group-skewed software pipeline + 4 producer warps (cp.async ring).
// bts: 1 word per (group,state): bts[g*BTSW + s], bit 31-(t&31).
// Boundary chain: warp w reads bnd[w-1][t-1] for its lane 0.
// =====================================================================
struct SmemB {
    float4 ring[RINGG * NQ * SROW];  // 105,600 B
    unsigned int bts[NGR * BTSW];    //  53,248 B
    float bnd[3][TT];                //  49,152 B
    float zz[SS * BDM];
    int bound[SS + 4];
    float hbuf[HH], cbuf[HH], gates[4 * HH];
    float rbuf[32], r2buf[32];
};

__device__ __forceinline__ float sigm(float v) { return 1.0f / (1.0f + __expf(-v)); }

__device__ __forceinline__ unsigned smem_u32(const void* p)
{
    return (unsigned)__cvta_generic_to_shared(p);
}

// 800 float4 per group over 128 producer threads
__device__ __forceinline__ void produce_group(SmemB* sm, int b, int p, int g)
{
    float4* dst = sm->ring + (size_t)(g & 7) * NQ * SROW;
    const float4* src = g_simsT + (size_t)b * NQ * TT + (size_t)g * GSTEP;
    for (int i = p; i < NQ * GSTEP; i += 128) {
        int q = i >> 5, r = i & 31;
        unsigned d = smem_u32(dst + q * SROW + r);
        const float4* gp = src + (size_t)q * TT + r;
        asm volatile("cp.async.cg.shared.global [%0], [%1], 16;"
                     :: "r"(d), "l"(gp) : "memory");
    }
    asm volatile("cp.async.commit_group;" ::: "memory");
    asm volatile("cp.async.wait_group 0;" ::: "memory");
}

template<int WID>
__device__ __forceinline__ void dp_group(SmemB* sm, int lane, int g,
                                         float& stR, float& lnR)
{
    const int sC = WID * 25 + (lane < 25 ? lane : 24);
    const float* simsc = (const float*)sm->ring
        + (size_t)(g & 7) * (NQ * SROW * 4)
        + (sC >> 2) * (SROW * 4) + (sC & 3);
    const float* bprev = (WID > 0) ? (&sm->bnd[WID - 1][0] + g * GSTEP - 1)
                                   : (const float*)0;
    float st = stR, left_next = lnR;
    unsigned acc = 0;

    if (g == 0) {
        // t = 0: init, no bit
        st = simsc[0];
        left_next = __shfl_up_sync(FULLM, st, 1);
        if (WID < 3 && lane == 24) sm->bnd[WID][0] = st;
#pragma unroll
        for (int u = 1; u < GSTEP; ++u) {
            float sv = simsc[u * 4];
            float left;
            if (WID > 0) { float bv = bprev[u]; left = (lane == 0) ? bv : left_next; }
            else           left = (lane == 0) ? 0.0f : left_next;
            float n = fmaxf(left, st) + sv;
            float nsh = __shfl_up_sync(FULLM, n, 1);
            acc |= (__float_as_uint(st - left) >> u) & (1u << (31 - u));
            if (WID < 3 && lane == 24) sm->bnd[WID][u] = n;
            st = n; left_next = nsh;
        }
    } else {
        const int tbase = g * GSTEP;
#pragma unroll
        for (int u = 0; u < GSTEP; ++u) {
            float sv = simsc[u * 4];
            float left;
            if (WID > 0) { float bv = bprev[u]; left = (lane == 0) ? bv : left_next; }
            else           left = (lane == 0) ? 0.0f : left_next;
            float n = fmaxf(left, st) + sv;
            float nsh = __shfl_up_sync(FULLM, n, 1);
            acc |= (__float_as_uint(st - left) >> u) & (1u << (31 - u));
            if (WID < 3 && lane == 24) sm->bnd[WID][tbase + u] = n;
            st = n; left_next = nsh;
        }
    }
    if (lane < 25) sm->bts[g * BTSW + WID * 25 + lane] = acc;
    stR = st; lnR = left_next;
}

__global__ void __launch_bounds__(256, 1)
k_dp(const float* __restrict__ w_ih, const float* __restrict__ w_hh,
     const float* __restrict__ b_ih, const float* __restrict__ b_hh,
     const float* __restrict__ wr1, const float* __restrict__ br1,
     const float* __restrict__ wr2, const float* __restrict__ br2,
     const float* __restrict__ wr3, const float* __restrict__ br3,
     float* __restrict__ out)
{
    extern __shared__ unsigned char smraw[];
    SmemB* sm = reinterpret_cast<SmemB*>(smraw);

    const int tid = threadIdx.x;
    const int b = blockIdx.x;
    const int wid = tid >> 5;
    const int lane = tid & 31;

    // ---- prologue: consumers init, producers stage groups 0..PF-1 ----
    if (wid < 4) {
        for (int i = tid; i < SS * BDM; i += 128) sm->zz[i] = 0.0f;
        for (int i = tid; i < HH; i += 128) { sm->hbuf[i] = 0.0f; sm->cbuf[i] = 0.0f; }
    } else {
        for (int gg = 0; gg < PF; ++gg) produce_group(sm, b, tid - 128, gg);
    }
    __syncthreads();

    // ---- skewed pipeline over 128 groups ----
    float st = 0.f, lnx = 0.f;
    for (int k = 0; k < NGR + 3; ++k) {
        if (wid < 4) {
            int g = k - wid;
            if (g >= 0 && g < NGR) {
                if      (wid == 0) dp_group<0>(sm, lane, g, st, lnx);
                else if (wid == 1) dp_group<1>(sm, lane, g, st, lnx);
                else if (wid == 2) dp_group<2>(sm, lane, g, st, lnx);
                else               dp_group<3>(sm, lane, g, st, lnx);
            }
        } else {
            int gp = k + PF;
            if (gp < NGR) produce_group(sm, b, tid - 128, gp);
        }
        __syncthreads();
    }

    // ---------------- warp-parallel backtrack ----------------
    if (tid < 32) {
        int s = SS - 1, cur = TT - 1;
        while (s > 0) {
            int gtop = cur >> 5;
            int ttstar = 0;
            for (int gb = gtop - 31; ; gb -= 32) {
                int g = gb + lane;
                unsigned w = 0;
                if (g >= 0 && g <= gtop) {
                    w = sm->bts[g * BTSW + s];
                    if (g == gtop) {
                        int pm = cur & 31;
                        w &= ~((1u << (31 - pm)) - 1u);
                    }
                }
                unsigned bal = __ballot_sync(FULLM, w != 0);
                if (bal) {
                    int hl = 31 - __clz((int)bal);
                    unsigned wh = __shfl_sync(FULLM, w, hl);
                    int pos = __ffs((int)wh) - 1;
                    ttstar = (gb + hl) * 32 + (31 - pos);
                    break;
                }
                if (gb <= 0 || gb * 32 <= s + 1) break;
            }
            int ttd = ttstar > s ? ttstar : s;
            if (lane == 0) sm->bound[s] = ttd;
            cur = ttd - 1;
            s--;
        }
        if (lane == 0) { sm->bound[0] = 0; sm->bound[SS] = TT; }
    }
    __syncthreads();

    // ---------------- segment sums ----------------
    {
        const int t0 = tid * (TT / 256);
        int lo = 0, hi = SS - 1;
        while (lo < hi) {
            int mid = (lo + hi + 1) >> 1;
            if (sm->bound[mid] <= t0) lo = mid; else hi = mid - 1;
        }
        int s = lo;
        int nxtb = sm->bound[s + 1];
        const float* zb = g_z + ((size_t)b * TT + t0) * BDM;
        float av[BDM];
#pragma unroll
        for (int d = 0; d < BDM; d++) av[d] = 0.0f;

        for (int kk = 0; kk < TT / 256; ++kk) {
            int t = t0 + kk;
            if (t >= nxtb) {
#pragma unroll
                for (int d = 0; d < BDM; d++) {
                    atomicAdd(&sm->zz[s * BDM + d], av[d]);
                    av[d] = 0.0f;
                }
                s++;
                nxtb = sm->bound[s + 1];
            }
#pragma unroll
            for (int d = 0; d < BDM; d++) av[d] += zb[kk * BDM + d];
        }
#pragma unroll
        for (int d = 0; d < BDM; d++) atomicAdd(&sm->zz[s * BDM + d], av[d]);
    }
    __syncthreads();

    for (int i = tid; i < SS * BDM; i += 256) {
        int s = i / BDM;
        sm->zz[i] = sm->zz[i] / (float)(sm->bound[s + 1] - sm->bound[s]);
    }
    __syncthreads();

    // ---------------- LSTM (weights in registers) ----------------
    float whr[HH], wir[BDM], bsr = 0.0f;
    if (tid < 4 * HH) {
#pragma unroll
        for (int kk = 0; kk < HH; kk++) whr[kk] = w_hh[tid * HH + kk];
#pragma unroll
        for (int d = 0; d < BDM; d++) wir[d] = w_ih[tid * BDM + d];
        bsr = b_ih[tid] + b_hh[tid];
    }

    for (int stp = 0; stp < SS; ++stp) {
        if (tid < 4 * HH) {
            float g = bsr;
            const float* xt = sm->zz + stp * BDM;
#pragma unroll
            for (int d = 0; d < BDM; d++) g += wir[d] * xt[d];
#pragma unroll
            for (int kk = 0; kk < HH; kk++) g += whr[kk] * sm->hbuf[kk];
            sm->gates[tid] = g;
        }
        __syncthreads();
        if (tid < HH) {
            float iv = sm->gates[tid];
            float fv = sm->gates[HH + tid];
            float gv = sm->gates[2 * HH + tid];
            float ov = sm->gates[3 * HH + tid];
            float cc = sigm(fv) * sm->cbuf[tid] + sigm(iv) * tanhf(gv);
            sm->cbuf[tid] = cc;
            sm->hbuf[tid] = sigm(ov) * tanhf(cc);
        }
        __syncthreads();
    }

    // ---------------- MLP head ----------------
    if (tid < DD) {
        float r = br1[tid];
#pragma unroll 10
        for (int kk = 0; kk < HH; kk++) r += wr1[tid * HH + kk] * sm->hbuf[kk];
        sm->rbuf[tid] = fmaxf(r, 0.0f);
    }
    __syncthreads();
    if (tid < DD) {
        float r = br2[tid];
#pragma unroll
        for (int kk = 0; kk < DD; kk++) r += wr2[tid * DD + kk] * sm->rbuf[kk];
        sm->r2buf[tid] = fmaxf(r, 0.0f);
    }
    __syncthreads();
    if (tid == 0) {
        float r = br3[0];
#pragma unroll
        for (int d = 0; d < DD; d++) r += wr3[d] * sm->r2buf[d];
        out[b] = r;
    }
}

// =====================================================================
// launch
// =====================================================================
extern "C" void kernel_launch(void* const* d_in, const int* in_sizes, int n_in,
                              void* d_out, int out_size)
{
    (void)in_sizes; (void)n_in; (void)out_size;
    const float* x    = (const float*)d_in[0];
    const float* c    = (const float*)d_in[1];
    const float* w1   = (const float*)d_in[2];
    const float* b1   = (const float*)d_in[3];
    const float* w2   = (const float*)d_in[4];
    const float* b2   = (const float*)d_in[5];
    const float* w3   = (const float*)d_in[6];
    const float* b3   = (const float*)d_in[7];
    const float* w_ih = (const float*)d_in[8];
    const float* w_hh = (const float*)d_in[9];
    const float* b_ih = (const float*)d_in[10];
    const float* b_hh = (const float*)d_in[11];
    const float* wr1  = (const float*)d_in[12];
    const float* br1  = (const float*)d_in[13];
    const float* wr2  = (const float*)d_in[14];
    const float* br2  = (const float*)d_in[15];
    const float* wr3  = (const float*)d_in[16];
    const float* br3  = (const float*)d_in[17];
    float* out = (float*)d_out;

    cudaFuncSetAttribute(k_dp, cudaFuncAttributeMaxDynamicSharedMemorySize,
                         (int)sizeof(SmemB));

    k_project<<<(BB * TT) / 256, 256>>>(x, c, w1, b1, w2, b2, w3, b3);
    k_dp<<<BB, 256, sizeof(SmemB)>>>(w_ih, w_hh, b_ih, b_hh,
                                     wr1, br1, wr2, br2, wr3, br3, out);
}

// round 12
// speedup vs baseline: 1.0471x; 1.0471x over previous
#include <cuda_runtime.h>
#include <math.h>

// ---------------- problem constants ----------------
#define BB   32
#define TT   4096
#define AD   128
#define SS   100
#define BDM  10
#define HH   50
#define DD   30
#define CH   64            // chunk = 64 timesteps
#define NCHK (TT / CH)     // 64 chunks
#define GSTEP 32
#define NGR  (TT / GSTEP)  // 128 groups
#define NQ   25
#define TROW 65            // padded tile row (float4)
#define BTSW 104           // bts words per group
#define FULLM 0xffffffffu

// ---------------- global scratch ----------------
__device__ __align__(16) float4 g_simsT[(size_t)BB * NQ * TT];  // [b][q][t]
__device__ __align__(16) float  g_z[(size_t)BB * TT * BDM];

// =====================================================================
// Kernel 1: z = mlp(x); sims stored quad-transposed [b][q][t]
// =====================================================================
__global__ void k_project(const float* __restrict__ x, const float* __restrict__ c,
                          const float* __restrict__ w1, const float* __restrict__ b1,
                          const float* __restrict__ w2, const float* __restrict__ b2,
                          const float* __restrict__ w3, const float* __restrict__ b3)
{
    __shared__ float w1s[BDM * AD];
    __shared__ float cs[BDM * SS];
    __shared__ float w2s[BDM * BDM], w3s[BDM * BDM];
    __shared__ float b1s[BDM], b2s[BDM], b3s[BDM];

    int tid = threadIdx.x;
    for (int i = tid; i < BDM * AD; i += 256) w1s[i] = w1[i];
    for (int i = tid; i < BDM * SS; i += 256) cs[i] = c[i];
    if (tid < BDM * BDM) { w2s[tid] = w2[tid]; w3s[tid] = w3[tid]; }
    if (tid < BDM) { b1s[tid] = b1[tid]; b2s[tid] = b2[tid]; b3s[tid] = b3[tid]; }
    __syncthreads();

    int gtid = blockIdx.x * 256 + tid;         // b*T + t
    int b = gtid >> 12;
    int t = gtid & (TT - 1);
    const float4* xr = (const float4*)(x + (size_t)gtid * AD);

    float z1[BDM];
#pragma unroll
    for (int d = 0; d < BDM; d++) z1[d] = b1s[d];

#pragma unroll 8
    for (int kk = 0; kk < AD / 4; ++kk) {
        float4 xv = xr[kk];
#pragma unroll
        for (int d = 0; d < BDM; d++) {
            float4 wv = ((const float4*)w1s)[d * (AD / 4) + kk];
            z1[d] += xv.x * wv.x + xv.y * wv.y + xv.z * wv.z + xv.w * wv.w;
        }
    }
#pragma unroll
    for (int d = 0; d < BDM; d++) z1[d] = fmaxf(z1[d], 0.0f);

    float z2[BDM];
#pragma unroll
    for (int d = 0; d < BDM; d++) {
        float a = b2s[d];
#pragma unroll
        for (int e = 0; e < BDM; e++) a += z1[e] * w2s[d * BDM + e];
        z2[d] = fmaxf(a, 0.0f);
    }
    float z3[BDM];
#pragma unroll
    for (int d = 0; d < BDM; d++) {
        float a = b3s[d];
#pragma unroll
        for (int e = 0; e < BDM; e++) a += z2[e] * w3s[d * BDM + e];
        z3[d] = a;
    }

    float* zo = g_z + (size_t)gtid * BDM;
#pragma unroll
    for (int d = 0; d < BDM; d++) zo[d] = z3[d];

#pragma unroll
    for (int q = 0; q < NQ; ++q) {
        float4 a = make_float4(0.f, 0.f, 0.f, 0.f);
#pragma unroll
        for (int d = 0; d < BDM; d++) {
            float zv = z3[d];
            float4 cv = ((const float4*)cs)[d * NQ + q];
            a.x += zv * cv.x; a.y += zv * cv.y;
            a.z += zv * cv.z; a.w += zv * cv.w;
        }
        g_simsT[((size_t)b * NQ + q) * TT + t] = a;   // coalesced over t
    }
}

// =====================================================================
// Kernel 2: consumers = warps 6 (states 0-49) & 7 (states 50-99),
// 2 states/lane, skewed by one 32-step group; producers = warps 0-5
// (cp.async, 4-chunk ring). bnd[1+t] carries state-49 history.
// bts: 1 word per (group,state): bts[g*BTSW+s], bit 31-(t&31).
// =====================================================================
struct SmemB {
    float4 tile[4][NQ * TROW];       // 104,000 B
    unsigned int bts[NGR * BTSW];    //  53,248 B
    float bnd[TT + 8];               //  16,416 B
    float zz[SS * BDM];
    int bound[SS + 4];
    float hbuf[HH], cbuf[HH], gates[4 * HH];
    float rbuf[32], r2buf[32];
};

__device__ __forceinline__ float sigm(float v) { return 1.0f / (1.0f + __expf(-v)); }

__device__ __forceinline__ unsigned smem_u32(const void* p)
{
    return (unsigned)__cvta_generic_to_shared(p);
}

// 1600 float4 per chunk over 192 producer threads
__device__ __forceinline__ void produce_chunk(SmemB* sm, int b, int p, int cn)
{
    float4* dst = sm->tile[cn & 3];
    const float4* src = g_simsT + (size_t)b * NQ * TT + (size_t)cn * CH;
    for (int i = p; i < NQ * CH; i += 192) {
        int q = i >> 6, r = i & 63;
        unsigned d = smem_u32(dst + q * TROW + r);
        const float4* gp = src + (size_t)q * TT + r;
        asm volatile("cp.async.cg.shared.global [%0], [%1], 16;"
                     :: "r"(d), "l"(gp) : "memory");
    }
    asm volatile("cp.async.commit_group;" ::: "memory");
    asm volatile("cp.async.wait_group 0;" ::: "memory");
}

// ---- warp 6: states 0-49 (sC = 2*ll), writes bnd ----
#define STEP0(U) do {                                                            \
    float2 sv = p[(r0 + (U)) * 2];                                               \
    float n1 = fmaxf(st0, st1) + sv.y;                                           \
    float nsh = __shfl_up_sync(FULLM, n1, 1);                                    \
    acc1 |= (__float_as_uint(st1 - st0) >> (U)) & (1u << (31 - (U)));            \
    float left = (lane == 0) ? 0.0f : left_next;                                 \
    acc0 |= (__float_as_uint(st0 - left) >> (U)) & (1u << (31 - (U)));           \
    float n0 = fmaxf(left, st0) + sv.x;                                          \
    if (lane == 24) sm->bnd[1 + g * GSTEP + (U)] = n1;                           \
    st0 = n0; st1 = n1; left_next = nsh; } while (0)

__device__ __forceinline__ void dp_group0(SmemB* sm, int lane, int g,
                                          float& s0R, float& s1R, float& lnR)
{
    const int ll = lane < 25 ? lane : 24;
    const int sC = 2 * ll;
    const float2* p = (const float2*)((const float*)sm->tile[(g >> 1) & 3]
                                      + (sC >> 2) * (TROW * 4) + (sC & 3));
    const int r0 = (g & 1) * GSTEP;
    float st0 = s0R, st1 = s1R, left_next = lnR;
    unsigned acc0 = 0, acc1 = 0;

    if (g == 0) {
        float2 sv = p[0];
        st0 = sv.x; st1 = sv.y;
        left_next = __shfl_up_sync(FULLM, st1, 1);
        if (lane == 24) sm->bnd[1] = st1;   // bnd[1+t], t=0
#pragma unroll
        for (int u = 1; u < GSTEP; ++u) STEP0(u);
    } else {
#pragma unroll
        for (int u = 0; u < GSTEP; ++u) STEP0(u);
    }
    if (lane < 25)
        *(uint2*)&sm->bts[g * BTSW + sC] = make_uint2(acc0, acc1);
    s0R = st0; s1R = st1; lnR = left_next;
}

// ---- warp 7: states 50-99, left of state 50 from bnd via bcast ----
#define STEP1(U) do {                                                            \
    float2 sv = p[(r0 + (U)) * 2];                                               \
    float n1 = fmaxf(st0, st1) + sv.y;                                           \
    float nsh = __shfl_up_sync(FULLM, n1, 1);                                    \
    acc1 |= (__float_as_uint(st1 - st0) >> (U)) & (1u << (31 - (U)));            \
    float bc = __shfl_sync(FULLM, bv, (U));                                      \
    float left = (lane == 0) ? bc : left_next;                                   \
    acc0 |= (__float_as_uint(st0 - left) >> (U)) & (1u << (31 - (U)));           \
    float n0 = fmaxf(left, st0) + sv.x;                                          \
    st0 = n0; st1 = n1; left_next = nsh; } while (0)

__device__ __forceinline__ void dp_group1(SmemB* sm, int lane, int g,
                                          float& s0R, float& s1R, float& lnR)
{
    const int ll = lane < 25 ? lane : 24;
    const int sC = 50 + 2 * ll;
    const float2* p = (const float2*)((const float*)sm->tile[(g >> 1) & 3]
                                      + (sC >> 2) * (TROW * 4) + (sC & 3));
    const int r0 = (g & 1) * GSTEP;
    float st0 = s0R, st1 = s1R, left_next = lnR;
    unsigned acc0 = 0, acc1 = 0;
    // bnd value for step t=g*32+u lives at index g*32+u (stored at 1+(t-1))
    float bv = sm->bnd[g * GSTEP + lane];

    if (g == 0) {
        float2 sv = p[0];
        st0 = sv.x; st1 = sv.y;
        left_next = __shfl_up_sync(FULLM, st1, 1);
#pragma unroll
        for (int u = 1; u < GSTEP; ++u) STEP1(u);
    } else {
#pragma unroll
        for (int u = 0; u < GSTEP; ++u) STEP1(u);
    }
    if (lane < 25)
        *(uint2*)&sm->bts[g * BTSW + sC] = make_uint2(acc0, acc1);
    s0R = st0; s1R = st1; lnR = left_next;
}

__global__ void __launch_bounds__(256, 1)
k_dp(const float* __restrict__ w_ih, const float* __restrict__ w_hh,
     const float* __restrict__ b_ih, const float* __restrict__ b_hh,
     const float* __restrict__ wr1, const float* __restrict__ br1,
     const float* __restrict__ wr2, const float* __restrict__ br2,
     const float* __restrict__ wr3, const float* __restrict__ br3,
     float* __restrict__ out)
{
    extern __shared__ unsigned char smraw[];
    SmemB* sm = reinterpret_cast<SmemB*>(smraw);

    const int tid = threadIdx.x;
    const int b = blockIdx.x;
    const int wid = tid >> 5;
    const int lane = tid & 31;

    // ---- prologue ----
    if (wid == 6) {
        for (int i = lane; i < SS * BDM; i += 32) sm->zz[i] = 0.0f;
        for (int i = lane; i < HH; i += 32) { sm->hbuf[i] = 0.0f; sm->cbuf[i] = 0.0f; }
    } else if (wid < 6) {
        produce_chunk(sm, b, tid, 0);
    }
    __syncthreads();

    // ---- skewed 2-warp DP over 64 chunks ----
    float st0 = 0.f, st1 = 0.f, lnx = 0.f;
    for (int ci = 0; ci < NCHK; ++ci) {
        if (wid == 6) {
            dp_group0(sm, lane, 2 * ci, st0, st1, lnx);
            asm volatile("bar.sync 1, 64;" ::: "memory");
            dp_group0(sm, lane, 2 * ci + 1, st0, st1, lnx);
        } else if (wid == 7) {
            if (ci > 0) dp_group1(sm, lane, 2 * ci - 1, st0, st1, lnx);
            asm volatile("bar.sync 1, 64;" ::: "memory");
            dp_group1(sm, lane, 2 * ci, st0, st1, lnx);
        } else {
            if (ci + 1 < NCHK) produce_chunk(sm, b, tid, ci + 1);
        }
        __syncthreads();
    }
    // epilogue: warp 7 finishes the last group
    if (wid == 7) dp_group1(sm, lane, NGR - 1, st0, st1, lnx);
    __syncthreads();

    // ---------------- warp-parallel backtrack ----------------
    if (tid < 32) {
        int s = SS - 1, cur = TT - 1;
        while (s > 0) {
            int gtop = cur >> 5;
            int ttstar = 0;
            for (int gb = gtop - 31; ; gb -= 32) {
                int g = gb + lane;
                unsigned w = 0;
                if (g >= 0 && g <= gtop) {
                    w = sm->bts[g * BTSW + s];
                    if (g == gtop) {
                        int pm = cur & 31;
                        w &= ~((1u << (31 - pm)) - 1u);
                    }
                }
                unsigned bal = __ballot_sync(FULLM, w != 0);
                if (bal) {
                    int hl = 31 - __clz((int)bal);
                    unsigned wh = __shfl_sync(FULLM, w, hl);
                    int pos = __ffs((int)wh) - 1;
                    ttstar = (gb + hl) * 32 + (31 - pos);
                    break;
                }
                if (gb <= 0 || gb * 32 <= s + 1) break;
            }
            int ttd = ttstar > s ? ttstar : s;
            if (lane == 0) sm->bound[s] = ttd;
            cur = ttd - 1;
            s--;
        }
        if (lane == 0) { sm->bound[0] = 0; sm->bound[SS] = TT; }
    }
    __syncthreads();

    // ---------------- segment sums ----------------
    {
        const int t0 = tid * (TT / 256);
        int lo = 0, hi = SS - 1;
        while (lo < hi) {
            int mid = (lo + hi + 1) >> 1;
            if (sm->bound[mid] <= t0) lo = mid; else hi = mid - 1;
        }
        int s = lo;
        int nxtb = sm->bound[s + 1];
        const float* zb = g_z + ((size_t)b * TT + t0) * BDM;
        float av[BDM];
#pragma unroll
        for (int d = 0; d < BDM; d++) av[d] = 0.0f;

        for (int kk = 0; kk < TT / 256; ++kk) {
            int t = t0 + kk;
            if (t >= nxtb) {
#pragma unroll
                for (int d = 0; d < BDM; d++) {
                    atomicAdd(&sm->zz[s * BDM + d], av[d]);
                    av[d] = 0.0f;
                }
                s++;
                nxtb = sm->bound[s + 1];
            }
#pragma unroll
            for (int d = 0; d < BDM; d++) av[d] += zb[kk * BDM + d];
        }
#pragma unroll
        for (int d = 0; d < BDM; d++) atomicAdd(&sm->zz[s * BDM + d], av[d]);
    }
    __syncthreads();

    for (int i = tid; i < SS * BDM; i += 256) {
        int s = i / BDM;
        sm->zz[i] = sm->zz[i] / (float)(sm->bound[s + 1] - sm->bound[s]);
    }
    __syncthreads();

    // ---------------- LSTM (weights in registers) ----------------
    float whr[HH], wir[BDM], bsr = 0.0f;
    if (tid < 4 * HH) {
#pragma unroll
        for (int kk = 0; kk < HH; kk++) whr[kk] = w_hh[tid * HH + kk];
#pragma unroll
        for (int d = 0; d < BDM; d++) wir[d] = w_ih[tid * BDM + d];
        bsr = b_ih[tid] + b_hh[tid];
    }

    for (int stp = 0; stp < SS; ++stp) {
        if (tid < 4 * HH) {
            float g = bsr;
            const float* xt = sm->zz + stp * BDM;
#pragma unroll
            for (int d = 0; d < BDM; d++) g += wir[d] * xt[d];
#pragma unroll
            for (int kk = 0; kk < HH; kk++) g += whr[kk] * sm->hbuf[kk];
            sm->gates[tid] = g;
        }
        __syncthreads();
        if (tid < HH) {
            float iv = sm->gates[tid];
            float fv = sm->gates[HH + tid];
            float gv = sm->gates[2 * HH + tid];
            float ov = sm->gates[3 * HH + tid];
            float cc = sigm(fv) * sm->cbuf[tid] + sigm(iv) * tanhf(gv);
            sm->cbuf[tid] = cc;
            sm->hbuf[tid] = sigm(ov) * tanhf(cc);
        }
        __syncthreads();
    }

    // ---------------- MLP head ----------------
    if (tid < DD) {
        float r = br1[tid];
#pragma unroll 10
        for (int kk = 0; kk < HH; kk++) r += wr1[tid * HH + kk] * sm->hbuf[kk];
        sm->rbuf[tid] = fmaxf(r, 0.0f);
    }
    __syncthreads();
    if (tid < DD) {
        float r = br2[tid];
#pragma unroll
        for (int kk = 0; kk < DD; kk++) r += wr2[tid * DD + kk] * sm->rbuf[kk];
        sm->r2buf[tid] = fmaxf(r, 0.0f);
    }
    __syncthreads();
    if (tid == 0) {
        float r = br3[0];
#pragma unroll
        for (int d = 0; d < DD; d++) r += wr3[d] * sm->r2buf[d];
        out[b] = r;
    }
}

// =====================================================================
// launch
// =====================================================================
extern "C" void kernel_launch(void* const* d_in, const int* in_sizes, int n_in,
                              void* d_out, int out_size)
{
    (void)in_sizes; (void)n_in; (void)out_size;
    const float* x    = (const float*)d_in[0];
    const float* c    = (const float*)d_in[1];
    const float* w1   = (const float*)d_in[2];
    const float* b1   = (const float*)d_in[3];
    const float* w2   = (const float*)d_in[4];
    const float* b2   = (const float*)d_in[5];
    const float* w3   = (const float*)d_in[6];
    const float* b3   = (const float*)d_in[7];
    const float* w_ih = (const float*)d_in[8];
    const float* w_hh = (const float*)d_in[9];
    const float* b_ih = (const float*)d_in[10];
    const float* b_hh = (const float*)d_in[11];
    const float* wr1  = (const float*)d_in[12];
    const float* br1  = (const float*)d_in[13];
    const float* wr2  = (const float*)d_in[14];
    const float* br2  = (const float*)d_in[15];
    const float* wr3  = (const float*)d_in[16];
    const float* br3  = (const float*)d_in[17];
    float* out = (float*)d_out;

    cudaFuncSetAttribute(k_dp, cudaFuncAttributeMaxDynamicSharedMemorySize,
                         (int)sizeof(SmemB));

    k_project<<<(BB * TT) / 256, 256>>>(x, c, w1, b1, w2, b2, w3, b3);
    k_dp<<<BB, 256, sizeof(SmemB)>>>(w_ih, w_hh, b_ih, b_hh,
                                     wr1, br1, wr2, br2, wr3, br3, out);
}